// round 7
// baseline (speedup 1.0000x reference)
#include <cuda_runtime.h>
#include <math.h>

#define D 128
#define MAXN 50000
#define MAXE 800000

// ---- persistent scratch (no allocation allowed) ----
__device__ float g_h[MAXN * D];     // current node features
__device__ float g_tmp[MAXN * D];   // (h @ W) * dinv[row]  (pre-scaled)
__device__ int   g_deg[MAXN];
__device__ float g_dinv[MAXN];
__device__ int   g_rowptr[MAXN + 1];
__device__ int   g_cursor[MAXN];
__device__ int   g_csr[MAXE];       // src node per CSR slot (grouped by dst)
__device__ int   g_ei64;            // 1 if edge_index is int64, 0 if int32
__device__ int   g_b64;             // 1 if batch is int64, 0 if int32

__device__ __forceinline__ int idx_at(const void* p, long long i, int is64) {
    return is64 ? (int)((const long long*)p)[i] : ((const int*)p)[i];
}

// ---------------------------------------------------------------------------
// zero degree array + init dtype flags (fused)
__global__ void k_zero_deg(int n) {
    int i = blockIdx.x * blockDim.x + threadIdx.x;
    if (i < n) g_deg[i] = 0;
    if (i == 0) { g_ei64 = 1; g_b64 = 1; }
}

// Parallel dtype detection: interpret first cnt/2 entries as int64; any value
// outside [0, range) => buffer is int32 (atomicAnd clears flag). Sampling
// stays within cnt*4 bytes, safe even if the buffer is int32-sized.
__global__ void k_detect(const void* __restrict__ buf, int cnt, int range, int which) {
    const long long* p = (const long long*)buf;
    int S = cnt / 2; if (S > 8192) S = 8192;
    int bad = 0;
    for (int i = blockIdx.x * blockDim.x + threadIdx.x; i < S;
         i += gridDim.x * blockDim.x) {
        long long v = p[i];
        if (v < 0 || v >= range) bad = 1;
    }
    if (__syncthreads_or(bad)) {
        if (threadIdx.x == 0) {
            if (which == 0) atomicAnd(&g_ei64, 0);
            else            atomicAnd(&g_b64, 0);
        }
    }
}

__global__ void k_count(const void* __restrict__ ei, int E, int N) {
    int e = blockIdx.x * blockDim.x + threadIdx.x;
    if (e < E) {
        int d = idx_at(ei, (long long)E + e, g_ei64);
        if (d >= 0 && d < N) atomicAdd(&g_deg[d], 1);
    }
}

// single-block scan over degrees -> rowptr, cursor (+ fused dinv)
__global__ void k_scan(int n, int E) {
    __shared__ int part[1024];
    int t = threadIdx.x;
    int chunk = (n + 1023) >> 10;
    int base = t * chunk;
    int s = 0;
    for (int i = 0; i < chunk; i++) {
        int idx = base + i;
        if (idx < n) s += g_deg[idx];
    }
    part[t] = s;
    __syncthreads();
    for (int off = 1; off < 1024; off <<= 1) {
        int v = 0;
        if (t >= off) v = part[t - off];
        __syncthreads();
        part[t] += v;
        __syncthreads();
    }
    int run = (t > 0) ? part[t - 1] : 0;
    for (int i = 0; i < chunk; i++) {
        int idx = base + i;
        if (idx < n) {
            int dg = g_deg[idx];
            g_rowptr[idx] = run;
            g_cursor[idx] = run;
            g_dinv[idx] = rsqrtf((float)(dg + 1));  // +1 self loop
            run += dg;
        }
    }
    if (t == 0) g_rowptr[n] = part[1023];
}

__global__ void k_scatter(const void* __restrict__ ei, int E, int N) {
    int e = blockIdx.x * blockDim.x + threadIdx.x;
    if (e < E) {
        int s = idx_at(ei, e, g_ei64);
        int d = idx_at(ei, (long long)E + e, g_ei64);
        if (s >= 0 && s < N && d >= 0 && d < N) {
            int p = atomicAdd(&g_cursor[d], 1);
            if (p >= 0 && p < E) g_csr[p] = s;
        }
    }
}

// ---------------------------------------------------------------------------
// packed f32x2 helpers (sm_103a FFMA2 — only reachable via PTX)
__device__ __forceinline__ unsigned long long f32x2_dup(float a) {
    unsigned long long r;
    asm("mov.b64 %0, {%1, %1};" : "=l"(r) : "f"(a));
    return r;
}
__device__ __forceinline__ void f32x2_fma(unsigned long long& acc,
                                          unsigned long long a,
                                          unsigned long long b) {
    asm("fma.rn.f32x2 %0, %1, %2, %0;" : "+l"(acc) : "l"(a), "l"(b));
}

// ---------------------------------------------------------------------------
// g_tmp = (A @ Wl) * dinv[row]   (A = X if useX else g_h), M x 128 @ 128 x 128
// 128x128 tile/block, 256 threads, 8x8 microtile as 8x4 packed f32x2 accums.
__global__ void __launch_bounds__(256) k_gemm(const float* __restrict__ X,
                                              const float* __restrict__ Wl,
                                              int M, int useX) {
    const float* A = useX ? X : g_h;
    __shared__ float sa[32][128];   // [k][m] (A transposed)
    __shared__ float sbuf[32][128]; // [k][n]
    int tid = threadIdx.x;
    int m0 = blockIdx.x * 128;
    int tx = tid & 15, ty = tid >> 4;

    unsigned long long acc2[8][4];
#pragma unroll
    for (int i = 0; i < 8; i++)
#pragma unroll
        for (int j = 0; j < 4; j++) acc2[i][j] = 0ull;

    for (int kt = 0; kt < 4; kt++) {
        // W tile: 32 rows x 128 cols = 1024 float4
#pragma unroll
        for (int i = 0; i < 4; i++) {
            int lin = tid + 256 * i;
            int r = lin >> 5;     // k-row within tile
            int c4 = lin & 31;    // float4 column
            float4 v = ((const float4*)(Wl + (size_t)(kt * 32 + r) * 128))[c4];
            ((float4*)&sbuf[r][0])[c4] = v;
        }
        // A tile (transposed in smem): 128 rows x 32 k = 1024 float4
#pragma unroll
        for (int i = 0; i < 4; i++) {
            int lin = tid + 256 * i;
            int r = lin >> 3;     // m-row in tile
            int k4 = lin & 7;     // float4 within 32-k slab
            float4 v = make_float4(0.f, 0.f, 0.f, 0.f);
            int row = m0 + r;
            if (row < M) v = ((const float4*)(A + (size_t)row * 128 + kt * 32))[k4];
            int k = k4 * 4;
            sa[k][r] = v.x; sa[k + 1][r] = v.y; sa[k + 2][r] = v.z; sa[k + 3][r] = v.w;
        }
        __syncthreads();
#pragma unroll
        for (int k = 0; k < 32; k++) {
            float4 a0 = *((const float4*)&sa[k][ty * 8]);
            float4 a1 = *((const float4*)&sa[k][ty * 8 + 4]);
            // B pairs loaded directly as 64-bit packed f32x2 (16B-aligned)
            const double2* pb = (const double2*)&sbuf[k][tx * 8];
            double2 b01 = pb[0];          // cols 8tx+0..3
            double2 b23 = pb[1];          // cols 8tx+4..7
            unsigned long long bv[4];
            bv[0] = __double_as_longlong(b01.x);
            bv[1] = __double_as_longlong(b01.y);
            bv[2] = __double_as_longlong(b23.x);
            bv[3] = __double_as_longlong(b23.y);
            float av[8] = {a0.x, a0.y, a0.z, a0.w, a1.x, a1.y, a1.z, a1.w};
#pragma unroll
            for (int i = 0; i < 8; i++) {
                unsigned long long ad = f32x2_dup(av[i]);
#pragma unroll
                for (int j = 0; j < 4; j++) f32x2_fma(acc2[i][j], ad, bv[j]);
            }
        }
        __syncthreads();
    }
#pragma unroll
    for (int i = 0; i < 8; i++) {
        int row = m0 + ty * 8 + i;
        if (row < M) {
            float dv = g_dinv[row];
            float o[8];
#pragma unroll
            for (int j = 0; j < 4; j++) {
                o[2 * j]     = __uint_as_float((unsigned)(acc2[i][j])) * dv;
                o[2 * j + 1] = __uint_as_float((unsigned)(acc2[i][j] >> 32)) * dv;
            }
            float4 o0 = make_float4(o[0], o[1], o[2], o[3]);
            float4 o1 = make_float4(o[4], o[5], o[6], o[7]);
            ((float4*)(g_tmp + (size_t)row * 128))[tx * 2] = o0;
            ((float4*)(g_tmp + (size_t)row * 128))[tx * 2 + 1] = o1;
        }
    }
}

// ---------------------------------------------------------------------------
// gather aggregation with pre-scaled tmp' = tmp*dinv:
// g_h[n] = relu( (tmp'[n] + sum_{s in in(n)} tmp'[s]) * dinv[n] + bias )
// one warp per node, float4 per lane (32 lanes * 4 = 128 features)
__global__ void __launch_bounds__(256) k_agg(const float* __restrict__ bias, int N, int E) {
    int wid = blockIdx.x * (blockDim.x >> 5) + (threadIdx.x >> 5);
    int lane = threadIdx.x & 31;
    if (wid >= N) return;
    float dn = g_dinv[wid];
    float4 acc = ((const float4*)(g_tmp + (size_t)wid * D))[lane];  // self term
    int beg = g_rowptr[wid], end = g_rowptr[wid + 1];
    if (beg < 0) beg = 0;
    if (end > E) end = E;
#pragma unroll 4
    for (int e = beg; e < end; e++) {
        int s = g_csr[e];
        float4 u = ((const float4*)(g_tmp + (size_t)s * D))[lane];
        acc.x += u.x; acc.y += u.y; acc.z += u.z; acc.w += u.w;
    }
    float4 bb = ((const float4*)bias)[lane];
    float4 r;
    r.x = fmaxf(fmaf(acc.x, dn, bb.x), 0.f);
    r.y = fmaxf(fmaf(acc.y, dn, bb.y), 0.f);
    r.z = fmaxf(fmaf(acc.z, dn, bb.z), 0.f);
    r.w = fmaxf(fmaf(acc.w, dn, bb.w), 0.f);
    ((float4*)(g_h + (size_t)wid * D))[lane] = r;
}

// ---------------------------------------------------------------------------
// mean pool per graph + linear head + log_softmax. one block per graph.
__global__ void k_pool(const void* __restrict__ batch,
                       const float* __restrict__ lin_w,
                       const float* __restrict__ lin_b,
                       float* hG_out, float* log_out,
                       int N, int nc) {
    int g = blockIdx.x, t = threadIdx.x;
    __shared__ int bounds[2];
    __shared__ float sh[D];
    __shared__ float sl[32];
    int is64 = g_b64;
    if (t == 0) {
        int lo = 0, hi = N;
        while (lo < hi) { int mid = (lo + hi) >> 1; if (idx_at(batch, mid, is64) < g) lo = mid + 1; else hi = mid; }
        bounds[0] = lo;
        hi = N;
        while (lo < hi) { int mid = (lo + hi) >> 1; if (idx_at(batch, mid, is64) <= g) lo = mid + 1; else hi = mid; }
        bounds[1] = lo;
    }
    __syncthreads();
    int beg = bounds[0], end = bounds[1];
    float sum = 0.f;
    for (int i = beg; i < end; i++) sum += g_h[(size_t)i * D + t];
    int c = end - beg;
    float cnt = (float)(c > 1 ? c : 1);
    float m = sum / cnt;
    if (hG_out) hG_out[(size_t)g * D + t] = m;
    sh[t] = m;
    __syncthreads();
    if (log_out) {
        if (t < nc) {
            float acc = lin_b[t];
            for (int k = 0; k < D; k++) acc += sh[k] * lin_w[k * nc + t];
            sl[t] = acc;
        }
        __syncthreads();
        if (t == 0) {
            float mx = -1e30f;
            for (int j = 0; j < nc; j++) mx = fmaxf(mx, sl[j]);
            float se = 0.f;
            for (int j = 0; j < nc; j++) se += expf(sl[j] - mx);
            float lse = mx + logf(se);
            for (int j = 0; j < nc; j++) log_out[(size_t)g * nc + j] = sl[j] - lse;
        }
    }
}

// ---------------------------------------------------------------------------
extern "C" void kernel_launch(void* const* d_in, const int* in_sizes, int n_in,
                              void* d_out, int out_size) {
    // Identify inputs by (distinct) element counts; fall back to position.
    const float* x = (const float*)d_in[0];
    const float* W = (const float*)d_in[1];
    const float* b = (const float*)d_in[2];
    const float* lin_w = (const float*)d_in[3];
    const float* lin_b = (const float*)d_in[4];
    const void* ei = d_in[5];
    const void* batch = d_in[6];
    int sz_x = in_sizes[0], sz_W = in_sizes[1], sz_lb = in_sizes[4],
        sz_ei = in_sizes[5], sz_batch = in_sizes[6];
    for (int i = 0; i < n_in; i++) {
        int s = in_sizes[i];
        switch (s) {
            case 6400000: x = (const float*)d_in[i]; sz_x = s; break;       // N*D
            case 49152:   W = (const float*)d_in[i]; sz_W = s; break;       // L*D*D
            case 384:     b = (const float*)d_in[i]; break;                 // L*D
            case 1280:    lin_w = (const float*)d_in[i]; break;             // D*nc
            case 10:      lin_b = (const float*)d_in[i]; sz_lb = s; break;  // nc
            case 1600000: ei = d_in[i]; sz_ei = s; break;                   // 2*E
            case 50000:   batch = d_in[i]; sz_batch = s; break;             // N
            default: break;
        }
    }

    int N = sz_x / D;
    int E = sz_ei / 2;
    int L = sz_W / (D * D);
    int nc = sz_lb;

    float* out = (float*)d_out;
    float* hG_out = 0;
    float* log_out = 0;
    int G = 0;
    if (out_size % (D + nc) == 0) {     // concatenated (hG, log_softmax)
        G = out_size / (D + nc);
        hG_out = out;
        log_out = out + (size_t)G * D;
    } else if (out_size % D == 0) {     // hG only
        G = out_size / D;
        hG_out = out;
    } else {                            // logits only
        G = out_size / nc;
        log_out = out;
    }

    int tE = (E + 255) / 256;
    int tN = (N + 255) / 256;

    k_zero_deg<<<tN, 256>>>(N);
    k_detect<<<16, 256>>>(ei, sz_ei, N, 0);
    k_detect<<<16, 256>>>(batch, sz_batch, G, 1);
    k_count<<<tE, 256>>>(ei, E, N);
    k_scan<<<1, 1024>>>(N, E);
    k_scatter<<<tE, 256>>>(ei, E, N);

    int gemm_blocks = (N + 127) / 128;
    int agg_blocks = (N + 7) / 8;       // 8 warps/block, warp per node
    for (int l = 0; l < L; l++) {
        k_gemm<<<gemm_blocks, 256>>>(x, W + (size_t)l * D * D, N, l == 0 ? 1 : 0);
        k_agg<<<agg_blocks, 256>>>(b + (size_t)l * D, N, E);
    }
    k_pool<<<G, D>>>(batch, lin_w, lin_b, hG_out, log_out, N, nc);
}